// round 16
// baseline (speedup 1.0000x reference)
#include <cuda_runtime.h>
#include <cuda_bf16.h>
#include <cstdint>
#include <cstddef>

#define TT 256
#define BB 64
#define HH 512
#define G6 3072
#define G5 2560
#define LAYER_W_STRIDE (512*3072 + 512*2560)   /* 2883584 */
#define WHH_OFF (512*3072)                      /* 1572864 */
#define NCTA 128

// lstm smem: [0,64KB) W at init, D partials after init | [64KB,192KB) h planes | mbars
#define OH_B 65536
#define OFF_MBAR_B 196608
#define SMEM_LSTM (OFF_MBAR_B + 128)

// gemm smem: 3 stages x (Ah|Al|Bh|Bl) x 16KB = 196608 B + mbars
#define SMEM_GMM (196608 + 64)

// ---------------- device scratch ----------------
__device__ float g_xt[(size_t)TT*HH*BB];          // layer input  [t][k][b]
__device__ float g_yt[(size_t)TT*HH*BB];          // layer output [t][k][b]
__device__ float g_xi[(size_t)TT*G6*BB];          // xi [t][g][b]
__device__ unsigned char g_hb0[4*32768];          // h split planes, dbuf A
__device__ unsigned char g_hb1[4*32768];          // h split planes, dbuf B
__device__ unsigned char g_whq[(size_t)4*128*65536]; // W_hh swizzled bf16 [l][grp][hi|lo]
__device__ unsigned g_cnt[4];                     // per-group monotonic counters
// xi-GEMM operand tiles (pre-swizzled SW128 blocked-atom, bf16 split)
__device__ uint4 g_wbh[(size_t)4*24*8192];
__device__ uint4 g_wbl[(size_t)4*24*8192];
__device__ uint4 g_xah[(size_t)128*8192];
__device__ uint4 g_xal[(size_t)128*8192];

// ---------------- helpers ----------------
__device__ __forceinline__ float sigmoidf_(float x) {
    return 1.0f / (1.0f + __expf(-x));
}
__device__ __forceinline__ void red_add_release_gpu(unsigned* p, unsigned v) {
    asm volatile("red.release.gpu.add.u32 [%0], %1;" :: "l"(p), "r"(v) : "memory");
}
__device__ __forceinline__ unsigned ld_acquire_gpu(const unsigned* p) {
    unsigned v;
    asm volatile("ld.acquire.gpu.u32 %0, [%1];" : "=r"(v) : "l"(p) : "memory");
    return v;
}
__device__ __forceinline__ unsigned smem_u32(const void* p) {
    unsigned a;
    asm("{ .reg .u64 t; cvta.to.shared.u64 t, %1; cvt.u32.u64 %0, t; }"
        : "=r"(a) : "l"(p));
    return a;
}
__device__ __forceinline__ void mbar_init(unsigned a, unsigned cnt) {
    asm volatile("mbarrier.init.shared.b64 [%0], %1;" :: "r"(a), "r"(cnt) : "memory");
}
__device__ __forceinline__ void mbar_expect_tx(unsigned a, unsigned bytes) {
    asm volatile("mbarrier.arrive.expect_tx.shared.b64 _, [%0], %1;"
                 :: "r"(a), "r"(bytes) : "memory");
}
__device__ __forceinline__ void bulk_g2s(unsigned dst, const void* src,
                                         unsigned bytes, unsigned mbar) {
    asm volatile("cp.async.bulk.shared::cluster.global.mbarrier::complete_tx::bytes "
                 "[%0], [%1], %2, [%3];"
                 :: "r"(dst), "l"(src), "r"(bytes), "r"(mbar) : "memory");
}
__device__ __forceinline__ void mbar_wait_parity(unsigned a, unsigned phase) {
    unsigned done;
    asm volatile(
        "{\n\t.reg .pred p;\n\t"
        "mbarrier.try_wait.parity.acquire.cta.shared::cta.b64 p, [%1], %2;\n\t"
        "selp.b32 %0, 1, 0, p;\n\t}"
        : "=r"(done) : "r"(a), "r"(phase) : "memory");
    if (!done) {
        asm volatile(
            "{\n\t.reg .pred P1;\n\t"
            "WL_%=:\n\t"
            "mbarrier.try_wait.parity.acquire.cta.shared::cta.b64 P1, [%0], %1, 0x989680;\n\t"
            "@P1 bra.uni WD_%=;\n\t"
            "bra.uni WL_%=;\n\t"
            "WD_%=:\n\t}"
            :: "r"(a), "r"(phase) : "memory");
    }
}
// swizzled byte offset of (row 0..127, col 0..511 bf16) in a 128x512 tile
__device__ __forceinline__ uint32_t tile_off(int row, int col) {
    uint32_t byte = (uint32_t)(((row >> 3) + (col >> 6)*16)*1024
                               + (row & 7)*128 + (col & 63)*2);
    return byte ^ ((byte >> 3) & 0x70);
}
// within one staged 64-col block (col < 64), 128 rows
__device__ __forceinline__ uint32_t blk_off(int row, int col) {
    uint32_t byte = (uint32_t)(((row >> 3) << 10) + ((row & 7) << 7) + (col << 1));
    return byte ^ ((byte >> 3) & 0x70);
}
// 64-row x 128-col h plane chunk (16KB)
__device__ __forceinline__ uint32_t hplane_off(int row, int kl) {
    uint32_t byte = (uint32_t)((((row >> 3) + ((kl >> 6) << 3)) << 10)
                               + ((row & 7) << 7) + ((kl & 63) << 1));
    return byte ^ ((byte >> 3) & 0x70);
}
// 32-row x 512-col weight plane (32KB)
__device__ __forceinline__ uint32_t wplane_off(int row, int col) {
    uint32_t byte = (uint32_t)((((row >> 3) + ((col >> 6) << 2)) << 10)
                               + ((row & 7) << 7) + ((col & 63) << 1));
    return byte ^ ((byte >> 3) & 0x70);
}
__device__ __forceinline__ void split_bf16(float v, unsigned& h, unsigned& l) {
    __nv_bfloat16 hb = __float2bfloat16(v);
    float r = v - __bfloat162float(hb);
    __nv_bfloat16 lb = __float2bfloat16(r);
    h = (unsigned)__bfloat16_as_ushort(hb);
    l = (unsigned)__bfloat16_as_ushort(lb);
}
#define LDMATRIX_X4(r0, r1, r2, r3, addr) \
    asm volatile("ldmatrix.sync.aligned.m8n8.x4.shared.b16 {%0,%1,%2,%3}, [%4];" \
                 : "=r"(r0), "=r"(r1), "=r"(r2), "=r"(r3) : "r"(addr))
#define MMA_BF16(d, a, b) \
    asm volatile("mma.sync.aligned.m16n8k16.row.col.f32.bf16.bf16.f32 " \
                 "{%0,%1,%2,%3}, {%4,%5,%6,%7}, {%8,%9}, {%0,%1,%2,%3};" \
                 : "+f"((d)[0]), "+f"((d)[1]), "+f"((d)[2]), "+f"((d)[3]) \
                 : "r"((a)[0]), "r"((a)[1]), "r"((a)[2]), "r"((a)[3]), \
                   "r"((b)[0]), "r"((b)[1]))

// ---------------- prep: (B,T,K) -> [t][k][b], masked ----------------
__global__ void prep_kernel(const float* __restrict__ in, const int* __restrict__ len) {
    int idx = blockIdx.x * blockDim.x + threadIdx.x;
    if (idx >= TT*HH*BB) return;
    int b = idx & 63;
    int k = (idx >> 6) & 511;
    int t = idx >> 15;
    float v = 0.f;
    if (t < len[b]) v = in[((size_t)b*TT + t)*HH + k];
    g_xt[idx] = v;
}

// ------- pack W_hh into per-CTA swizzled split-bf16 B tiles [q32][k512] -------
__global__ void packwq_kernel(const float* __restrict__ weight) {
    int idx = blockIdx.x * blockDim.x + threadIdx.x;
    if (idx >= 4*128*32*64) return;
    int cu  = idx & 63;
    int row = (idx >> 6) & 31;
    int gq  = (idx >> 11) & 127;
    int l   = idx >> 18;
    unsigned h[8], lo[8];
    if (row < 20) {
        int hid = gq*4 + row/5;
        int g   = row % 5;
        const float* wsrc = weight + (size_t)l*LAYER_W_STRIDE + WHH_OFF;
        #pragma unroll
        for (int j = 0; j < 8; j++) {
            float v = wsrc[(size_t)(cu*8 + j)*G5 + g*512 + hid];
            split_bf16(v, h[j], lo[j]);
        }
    } else {
        #pragma unroll
        for (int j = 0; j < 8; j++) { h[j] = 0; lo[j] = 0; }
    }
    uint32_t off = wplane_off(row, cu*8);
    unsigned char* dst = g_whq + (size_t)(l*128 + gq)*65536;
    *(uint4*)(dst + off)         = make_uint4(h[0]|(h[1]<<16),  h[2]|(h[3]<<16),
                                              h[4]|(h[5]<<16),  h[6]|(h[7]<<16));
    *(uint4*)(dst + 32768 + off) = make_uint4(lo[0]|(lo[1]<<16), lo[2]|(lo[3]<<16),
                                              lo[4]|(lo[5]<<16), lo[6]|(lo[7]<<16));
}

// ---------------- pack W_ih^T into swizzled split-bf16 B tiles [n][k] ---------
__global__ void packwb_kernel(const float* __restrict__ weight) {
    int idx = blockIdx.x * blockDim.x + threadIdx.x;
    if (idx >= 4*24*128*64) return;
    int cu  = idx & 63;
    int row = (idx >> 6) & 127;
    int nt  = (idx >> 13) % 24;
    int l   = (idx >> 13) / 24;
    int g = nt*128 + row;
    const float* wsrc = weight + (size_t)l*LAYER_W_STRIDE;
    unsigned h[8], lo[8];
    #pragma unroll
    for (int j = 0; j < 8; j++) {
        float v = wsrc[(size_t)(cu*8 + j)*G6 + g];
        split_bf16(v, h[j], lo[j]);
    }
    size_t off = (size_t)(l*24 + nt)*8192 + (tile_off(row, cu*8) >> 4);
    g_wbh[off] = make_uint4(h[0]|(h[1]<<16),  h[2]|(h[3]<<16),
                            h[4]|(h[5]<<16),  h[6]|(h[7]<<16));
    g_wbl[off] = make_uint4(lo[0]|(lo[1]<<16), lo[2]|(lo[3]<<16),
                            lo[4]|(lo[5]<<16), lo[6]|(lo[7]<<16));
}

// ------- convert layer input -> swizzled split-bf16 A tiles [m][k] -----------
__global__ void conva_kernel(const float* __restrict__ xsrc,
                             const int* __restrict__ len, int rev) {
    int idx = blockIdx.x * blockDim.x + threadIdx.x;
    if (idx >= 128*128*64) return;
    int cu   = idx & 63;
    int row  = (idx >> 6) & 127;
    int tile = idx >> 13;
    int b = row & 63;
    int t = tile*2 + (row >> 6);
    if (rev) { int L = len[b]; if (t < L) t = L - 1 - t; }
    unsigned h[8], lo[8];
    #pragma unroll
    for (int j = 0; j < 8; j++) {
        float v = xsrc[((size_t)t*HH + cu*8 + j)*BB + b];
        split_bf16(v, h[j], lo[j]);
    }
    size_t off = (size_t)tile*8192 + (tile_off(row, cu*8) >> 4);
    g_xah[off] = make_uint4(h[0]|(h[1]<<16),  h[2]|(h[3]<<16),
                            h[4]|(h[5]<<16),  h[6]|(h[7]<<16));
    g_xal[off] = make_uint4(lo[0]|(lo[1]<<16), lo[2]|(lo[3]<<16),
                            lo[4]|(lo[5]<<16), lo[6]|(lo[7]<<16));
}

// ---------------- bf16-split mma.sync xi GEMM (3-stage, R15 passing) ---------
__global__ __launch_bounds__(256)
void gemm_mma_kernel(const uint8_t* __restrict__ Ah, const uint8_t* __restrict__ Al,
                     const uint8_t* __restrict__ Bh, const uint8_t* __restrict__ Bl,
                     float* __restrict__ XI)
{
    extern __shared__ __align__(1024) uint8_t smg[];
    int tid = threadIdx.x;
    int lane = tid & 31, wid = tid >> 5;
    int wm = wid & 3, wn = wid >> 2;
    int mt = blockIdx.x, nt = blockIdx.y;
    unsigned sm = smem_u32(smg);
    unsigned mbf = sm + 196608u;

    if (tid == 0) {
        mbar_init(mbf, 1); mbar_init(mbf + 8, 1); mbar_init(mbf + 16, 1);
        asm volatile("fence.proxy.async.shared::cta;" ::: "memory");
    }
    __syncthreads();

    const uint8_t* aH = Ah + (size_t)mt*131072;
    const uint8_t* aL = Al + (size_t)mt*131072;
    const uint8_t* bH = Bh + (size_t)nt*131072;
    const uint8_t* bL = Bl + (size_t)nt*131072;

    if (tid == 0) {
        #pragma unroll
        for (int s = 0; s < 3; s++) {
            unsigned sb = sm + (unsigned)s*65536u;
            mbar_expect_tx(mbf + 8*s, 65536u);
            bulk_g2s(sb,           aH + s*16384, 16384u, mbf + 8*s);
            bulk_g2s(sb + 16384u,  aL + s*16384, 16384u, mbf + 8*s);
            bulk_g2s(sb + 32768u,  bH + s*16384, 16384u, mbf + 8*s);
            bulk_g2s(sb + 49152u,  bL + s*16384, 16384u, mbf + 8*s);
        }
    }

    float acc[2][8][4];
    #pragma unroll
    for (int mi = 0; mi < 2; mi++)
        #pragma unroll
        for (int nj = 0; nj < 8; nj++)
            #pragma unroll
            for (int q = 0; q < 4; q++) acc[mi][nj][q] = 0.f;

    int r  = lane & 7;
    int ts = lane >> 3;
    int arow0 = wm*32 + r + ((ts & 1) << 3);
    int akadd = (ts >> 1) << 3;
    int brow0 = wn*64 + r + ((ts >> 1) << 3);
    int bkadd = (ts & 1) << 3;

    for (int s = 0; s < 8; s++) {
        int p = s % 3;
        unsigned ph = (unsigned)((s / 3) & 1);
        mbar_wait_parity(mbf + 8*p, ph);
        unsigned sb  = sm + (unsigned)p*65536u;
        unsigned sAh = sb, sAl = sb + 16384u;
        unsigned sBh = sb + 32768u, sBl = sb + 49152u;

        #pragma unroll
        for (int j = 0; j < 4; j++) {
            int kc = j*16 + akadd;
            uint32_t ah0[4], ah1[4], al0[4], al1[4];
            {
                unsigned o0 = blk_off(arow0,      kc);
                unsigned o1 = blk_off(arow0 + 16, kc);
                LDMATRIX_X4(ah0[0], ah0[1], ah0[2], ah0[3], sAh + o0);
                LDMATRIX_X4(ah1[0], ah1[1], ah1[2], ah1[3], sAh + o1);
                LDMATRIX_X4(al0[0], al0[1], al0[2], al0[3], sAl + o0);
                LDMATRIX_X4(al1[0], al1[1], al1[2], al1[3], sAl + o1);
            }
            int kb = j*16 + bkadd;
            uint32_t bh[8][2], bl[8][2];
            #pragma unroll
            for (int p4 = 0; p4 < 4; p4++) {
                unsigned ob = blk_off(brow0 + p4*16, kb);
                LDMATRIX_X4(bh[2*p4][0], bh[2*p4][1], bh[2*p4+1][0], bh[2*p4+1][1],
                            sBh + ob);
                LDMATRIX_X4(bl[2*p4][0], bl[2*p4][1], bl[2*p4+1][0], bl[2*p4+1][1],
                            sBl + ob);
            }
            #pragma unroll
            for (int nj = 0; nj < 8; nj++) {
                MMA_BF16(acc[0][nj], ah0, bh[nj]);
                MMA_BF16(acc[1][nj], ah1, bh[nj]);
                MMA_BF16(acc[0][nj], ah0, bl[nj]);
                MMA_BF16(acc[1][nj], ah1, bl[nj]);
                MMA_BF16(acc[0][nj], al0, bh[nj]);
                MMA_BF16(acc[1][nj], al1, bh[nj]);
            }
        }
        __syncthreads();
        if (tid == 0 && s + 3 < 8) {
            int s2 = s + 3;
            mbar_expect_tx(mbf + 8*p, 65536u);
            bulk_g2s(sb,          aH + s2*16384, 16384u, mbf + 8*p);
            bulk_g2s(sb + 16384u, aL + s2*16384, 16384u, mbf + 8*p);
            bulk_g2s(sb + 32768u, bH + s2*16384, 16384u, mbf + 8*p);
            bulk_g2s(sb + 49152u, bL + s2*16384, 16384u, mbf + 8*p);
        }
    }

    int g4 = lane >> 2, t4 = lane & 3;
    #pragma unroll
    for (int mi = 0; mi < 2; mi++) {
        #pragma unroll
        for (int half = 0; half < 2; half++) {
            int m = mt*128 + wm*32 + mi*16 + g4 + half*8;
            int t = m >> 6, b = m & 63;
            float* xo = XI + ((size_t)t*G6 + nt*128 + wn*64 + t4*2)*64 + b;
            #pragma unroll
            for (int nj = 0; nj < 8; nj++) {
                xo[(size_t)(nj*8)*64]       = acc[mi][nj][half*2];
                xo[(size_t)(nj*8 + 1)*64]   = acc[mi][nj][half*2 + 1];
            }
        }
    }
}

// ---------------- persistent per-layer recurrence ----------------
// New math mapping: warp (kh 0..3, bm 0..1) computes D[m32(b) x n32(q)] over
// its own k128 chunk only. B (weights hi+lo) lives in REGISTERS for the whole
// layer (loaded once). Each A element read by exactly one warp; D partials
// (per kh) go to smem (pitch 33) overlaid on the dead W region; gates phase
// reduces over the 4 kh partials. Same chunks/mbarriers/counters as R15.
__global__ __launch_bounds__(288)
void lstm_layer_kernel(const float* __restrict__ xi_base,
                       const unsigned char* __restrict__ wq,
                       const float* __restrict__ bias,
                       const int*   __restrict__ len,
                       unsigned char* __restrict__ hbuf0,
                       unsigned char* __restrict__ hbuf1,
                       float* __restrict__ y,
                       int rev)
{
    extern __shared__ float smf[];
    int tid = threadIdx.x;
    int hid0 = blockIdx.x * 4;
    int grp  = blockIdx.x >> 5;

    unsigned smbase = smem_u32(smf);
    unsigned smW    = smbase;               // 64KB at init; D partials after
    unsigned smH    = smbase + OH_B;
    unsigned mbar0  = smbase + OFF_MBAR_B;  // 8 mbars: [ch].hi @16ch, [ch].lo @16ch+8

    int lane = tid & 31, wid = tid >> 5;
    int kh = wid & 3, bm = wid >> 2;        // valid for wid<8
    int hl_o = (tid >> 6) & 3;
    int b_o  = tid & 63;
    int hid_o = hid0 + hl_o;

    // one-time: weights -> smem (64KB linear; pre-swizzled in global)
    if (tid < 256) {
        const uint4* ws = (const uint4*)(wq + (size_t)blockIdx.x*65536);
        uint4* wd = (uint4*)smf;
        #pragma unroll
        for (int i = 0; i < 16; i++) wd[tid + i*256] = ws[tid + i*256];
    }
    if (tid == 256) {
        #pragma unroll
        for (int c = 0; c < 8; c++) mbar_init(mbar0 + 8*c, 1);
        asm volatile("fence.proxy.async.shared::cta;" ::: "memory");
    }

    float bval[5] = {0.f, 0.f, 0.f, 0.f, 0.f};
    int L = 0;
    float xiv[6] = {0.f, 0.f, 0.f, 0.f, 0.f, 0.f};
    if (tid < 256) {
        #pragma unroll
        for (int g = 0; g < 5; g++) bval[g] = bias[g*512 + hid_o];
        L = len[b_o];
        #pragma unroll
        for (int g = 0; g < 6; g++)
            xiv[g] = __ldcs(xi_base + (size_t)(g*512 + hid_o)*BB + b_o);
    }
    float c = 0.0f;

    unsigned char* hin  = hbuf0;
    unsigned char* hout = hbuf1;

    int r  = lane & 7;
    int ts = lane >> 3;
    int ak    = (ts >> 1) << 3;
    int arow0 = bm*32 + r + ((ts & 1) << 3);
    int arow1 = arow0 + 16;
    int brow_base = r + ((ts >> 1) << 3);
    int bkk   = (ts & 1) << 3;

    __syncthreads();                        // W smem + mbar init visible

    // ---- load B (weight) fragments into registers, once per layer ----
    uint32_t bfh[8][4][2], bfl[8][4][2];
    if (tid < 256) {
        #pragma unroll
        for (int j = 0; j < 8; j++) {
            int kg = kh*128 + j*16 + bkk;
            #pragma unroll
            for (int ng = 0; ng < 2; ng++) {
                unsigned bo = wplane_off(ng*16 + brow_base, kg);
                LDMATRIX_X4(bfh[j][2*ng][0], bfh[j][2*ng][1],
                            bfh[j][2*ng+1][0], bfh[j][2*ng+1][1], smW + bo);
                LDMATRIX_X4(bfl[j][2*ng][0], bfl[j][2*ng][1],
                            bfl[j][2*ng+1][0], bfl[j][2*ng+1][1],
                            smW + 32768u + bo);
            }
        }
    }
    __syncthreads();                        // all W reads done; region becomes D

    // stage step 0 (h[-1] = zeros)
    if (tid == 256) {
        #pragma unroll
        for (int ch = 0; ch < 4; ch++) {
            mbar_expect_tx(mbar0 + 16*ch, 16384u);
            bulk_g2s(smH + ch*32768u, hin + ch*32768, 16384u, mbar0 + 16*ch);
            mbar_expect_tx(mbar0 + 16*ch + 8, 16384u);
            bulk_g2s(smH + ch*32768u + 16384u, hin + ch*32768 + 16384, 16384u,
                     mbar0 + 16*ch + 8);
        }
    }

    for (int s = 0; s < TT; s++) {
        unsigned phase = (unsigned)(s & 1);

        if (tid < 256) {
            float acc[2][4][4];
            #pragma unroll
            for (int mi = 0; mi < 2; mi++)
                #pragma unroll
                for (int n = 0; n < 4; n++)
                    #pragma unroll
                    for (int q = 0; q < 4; q++) acc[mi][n][q] = 0.f;

            unsigned sAh = smH + kh*32768u;
            unsigned sAl = sAh + 16384u;

            mbar_wait_parity(mbar0 + 16*kh, phase);       // hi plane
            #pragma unroll
            for (int j = 0; j < 8; j++) {
                uint32_t a0[4], a1[4];
                LDMATRIX_X4(a0[0], a0[1], a0[2], a0[3],
                            sAh + hplane_off(arow0, j*16 + ak));
                LDMATRIX_X4(a1[0], a1[1], a1[2], a1[3],
                            sAh + hplane_off(arow1, j*16 + ak));
                #pragma unroll
                for (int n = 0; n < 4; n++) {
                    MMA_BF16(acc[0][n], a0, bfh[j][n]);
                    MMA_BF16(acc[1][n], a1, bfh[j][n]);
                    MMA_BF16(acc[0][n], a0, bfl[j][n]);
                    MMA_BF16(acc[1][n], a1, bfl[j][n]);
                }
            }
            mbar_wait_parity(mbar0 + 16*kh + 8, phase);   // lo plane
            #pragma unroll
            for (int j = 0; j < 8; j++) {
                uint32_t a0[4], a1[4];
                LDMATRIX_X4(a0[0], a0[1], a0[2], a0[3],
                            sAl + hplane_off(arow0, j*16 + ak));
                LDMATRIX_X4(a1[0], a1[1], a1[2], a1[3],
                            sAl + hplane_off(arow1, j*16 + ak));
                #pragma unroll
                for (int n = 0; n < 4; n++) {
                    MMA_BF16(acc[0][n], a0, bfh[j][n]);
                    MMA_BF16(acc[1][n], a1, bfh[j][n]);
                }
            }

            // store D partials: part[kh][b(64)][q(33 pitch)]
            float* dp = smf + kh*64*33;
            int r0 = lane >> 2, c0 = (lane & 3)*2;
            #pragma unroll
            for (int mi = 0; mi < 2; mi++) {
                int b0 = bm*32 + mi*16 + r0;
                #pragma unroll
                for (int n = 0; n < 4; n++) {
                    int q0 = n*8 + c0;
                    dp[b0*33 + q0]         = acc[mi][n][0];
                    dp[b0*33 + q0 + 1]     = acc[mi][n][1];
                    dp[(b0+8)*33 + q0]     = acc[mi][n][2];
                    dp[(b0+8)*33 + q0 + 1] = acc[mi][n][3];
                }
            }
        }
        __syncthreads();                              // sync A

        float hn = 0.f;
        if (tid < 256) {
            float gv[5];
            #pragma unroll
            for (int g = 0; g < 5; g++) gv[g] = xiv[g] + bval[g];
            const float* dbase = smf + b_o*33 + hl_o*5;
            #pragma unroll
            for (int k2 = 0; k2 < 4; k2++) {
                const float* p = dbase + k2*64*33;
                #pragma unroll
                for (int g = 0; g < 5; g++) gv[g] += p[g];
            }

            float ig = sigmoidf_(gv[0]);
            float fg = sigmoidf_(gv[1]);
            float gc = tanhf(gv[2]);
            float og = sigmoidf_(gv[3]);
            float rg = sigmoidf_(gv[4]);
            float lin = xiv[5];

            float cn;
            if (s < L) {
                cn = fg*c + ig*gc;
                hn = rg*(og*tanhf(cn)) + (1.f - rg)*lin;
            } else {
                cn = 0.f; hn = 0.f;
            }
            c = cn;
            unsigned hi16, lo16;
            split_bf16(hn, hi16, lo16);
            int chn = hid_o >> 7, kl = hid_o & 127;
            uint32_t loc = hplane_off(b_o, kl);
            *(uint16_t*)(hout + chn*32768 + loc)          = (uint16_t)hi16;
            *(uint16_t*)(hout + chn*32768 + 16384 + loc)  = (uint16_t)lo16;
        }
        __syncthreads();                              // sync B

        int dst = rev ? ((s < L) ? (L - 1 - s) : s) : s;

        if (s != TT-1) {
            if (tid == 0)
                red_add_release_gpu(&g_cnt[grp], 1u);

            if (tid < 256) {
                y[((size_t)dst*HH + hid_o)*BB + b_o] = hn;
                const float* xs = xi_base + (size_t)(s+1)*G6*BB;
                #pragma unroll
                for (int g = 0; g < 6; g++)
                    xiv[g] = __ldcs(xs + (size_t)(g*512 + hid_o)*BB + b_o);
            }

            if (tid == 256) {
                const unsigned char* hsrc = hout;
                unsigned target = 32u * (unsigned)(s + 1);
                #pragma unroll
                for (int ch = 0; ch < 4; ch++) {
                    while (ld_acquire_gpu(&g_cnt[ch]) < target) __nanosleep(32);
                    mbar_expect_tx(mbar0 + 16*ch, 16384u);
                    bulk_g2s(smH + ch*32768u, hsrc + ch*32768, 16384u,
                             mbar0 + 16*ch);
                    mbar_expect_tx(mbar0 + 16*ch + 8, 16384u);
                    bulk_g2s(smH + ch*32768u + 16384u, hsrc + ch*32768 + 16384,
                             16384u, mbar0 + 16*ch + 8);
                }
            }
        } else if (tid < 256) {
            y[((size_t)dst*HH + hid_o)*BB + b_o] = hn;
        }

        unsigned char* tmp = hin; hin = hout; hout = tmp;
    }
}

// ---------------- final: [t][k][b] -> (B,T,K) ----------------
__global__ void out_kernel(const float* __restrict__ xt, float* __restrict__ out) {
    int idx = blockIdx.x * blockDim.x + threadIdx.x;
    if (idx >= TT*HH*BB) return;
    int k = idx & 511;
    int t = (idx >> 9) & 255;
    int b = idx >> 17;
    out[idx] = xt[((size_t)t*HH + k)*BB + b];
}

// ---------------- launch ----------------
extern "C" void kernel_launch(void* const* d_in, const int* in_sizes, int n_in,
                              void* d_out, int out_size)
{
    const float* inputs = nullptr;
    const float* weight = nullptr;
    const float* biasp  = nullptr;
    const int*   len    = nullptr;
    for (int i = 0; i < n_in; i++) {
        switch (in_sizes[i]) {
            case TT*BB*HH:  inputs = (const float*)d_in[i]; break;  // 8388608
            case 11534336:  weight = (const float*)d_in[i]; break;
            case 4*G5:      biasp  = (const float*)d_in[i]; break;  // 10240
            case BB:        len    = (const int*)  d_in[i]; break;  // 64
        }
    }

    float *pxt, *pyt, *pxi;
    unsigned char *phb0, *phb1, *pwhq;
    unsigned* pcnt;
    uint4 *pwbh, *pwbl, *pxah, *pxal;
    cudaGetSymbolAddress((void**)&pxt,  g_xt);
    cudaGetSymbolAddress((void**)&pyt,  g_yt);
    cudaGetSymbolAddress((void**)&pxi,  g_xi);
    cudaGetSymbolAddress((void**)&phb0, g_hb0);
    cudaGetSymbolAddress((void**)&phb1, g_hb1);
    cudaGetSymbolAddress((void**)&pwhq, g_whq);
    cudaGetSymbolAddress((void**)&pcnt, g_cnt);
    cudaGetSymbolAddress((void**)&pwbh, g_wbh);
    cudaGetSymbolAddress((void**)&pwbl, g_wbl);
    cudaGetSymbolAddress((void**)&pxah, g_xah);
    cudaGetSymbolAddress((void**)&pxal, g_xal);

    cudaFuncSetAttribute(lstm_layer_kernel,
                         cudaFuncAttributeMaxDynamicSharedMemorySize, SMEM_LSTM);
    cudaFuncSetAttribute(gemm_mma_kernel,
                         cudaFuncAttributeMaxDynamicSharedMemorySize, SMEM_GMM);

    prep_kernel<<<(TT*HH*BB + 255)/256, 256>>>(inputs, len);
    packwq_kernel<<<(4*128*32*64)/256, 256>>>(weight);
    packwb_kernel<<<(4*24*128*64)/256, 256>>>(weight);

    float* xin  = pxt;
    float* yout = pyt;
    for (int l = 0; l < 4; l++) {
        int rev = l & 1;
        conva_kernel<<<(128*128*64)/256, 256>>>(xin, len, rev);
        gemm_mma_kernel<<<dim3(128, 24), 256, SMEM_GMM>>>(
            (const uint8_t*)pxah, (const uint8_t*)pxal,
            (const uint8_t*)(pwbh + (size_t)l*24*8192),
            (const uint8_t*)(pwbl + (size_t)l*24*8192),
            pxi);
        cudaMemsetAsync(phb0, 0, 4*32768);
        cudaMemsetAsync(pcnt, 0, 4*sizeof(unsigned));
        lstm_layer_kernel<<<NCTA, 288, SMEM_LSTM>>>(
            pxi, pwhq + (size_t)l*128*65536, biasp + (size_t)l*G5,
            len, phb0, phb1, yout, rev);
        float* tmp = xin; xin = yout; yout = tmp;
    }
    out_kernel<<<(TT*HH*BB + 255)/256, 256>>>(xin, (float*)d_out);
}

// round 17
// speedup vs baseline: 1.5618x; 1.5618x over previous
#include <cuda_runtime.h>
#include <cuda_bf16.h>
#include <cstdint>
#include <cstddef>

#define TT 256
#define BB 64
#define HH 512
#define G6 3072
#define G5 2560
#define LAYER_W_STRIDE (512*3072 + 512*2560)   /* 2883584 */
#define WHH_OFF (512*3072)                      /* 1572864 */
#define NCTA 128

// lstm smem (floats): weights 64KB | h planes 128KB | D buf 8.5KB | mbars
#define OWQ_F 0
#define OH_F  16384
#define OD_F  49152
#define OFF_MBAR_B ((49152 + 2176) * 4)   /* 205312 */
#define SMEM_LSTM (OFF_MBAR_B + 64)       /* 8 mbarriers */

// gemm smem: 3 stages x (Ah|Al|Bh|Bl) x 16KB = 196608 B + mbars
#define SMEM_GMM (196608 + 64)

// ---------------- device scratch ----------------
__device__ float g_xt[(size_t)TT*HH*BB];          // layer input  [t][k][b]
__device__ float g_yt[(size_t)TT*HH*BB];          // layer output [t][k][b]
__device__ float g_xi[(size_t)TT*G6*BB];          // xi [t][g][b]
__device__ unsigned char g_hb0[4*32768];          // h split planes, dbuf A
__device__ unsigned char g_hb1[4*32768];          // h split planes, dbuf B
__device__ unsigned char g_whq[(size_t)4*128*65536]; // W_hh swizzled bf16 [l][grp][hi|lo]
__device__ unsigned g_cnt[4];                     // per-group monotonic counters
// xi-GEMM operand tiles (pre-swizzled SW128 blocked-atom, bf16 split)
__device__ uint4 g_wbh[(size_t)4*24*8192];
__device__ uint4 g_wbl[(size_t)4*24*8192];
__device__ uint4 g_xah[(size_t)128*8192];
__device__ uint4 g_xal[(size_t)128*8192];

// ---------------- helpers ----------------
__device__ __forceinline__ float sigmoidf_(float x) {
    return 1.0f / (1.0f + __expf(-x));
}
__device__ __forceinline__ void red_add_release_gpu(unsigned* p, unsigned v) {
    asm volatile("red.release.gpu.add.u32 [%0], %1;" :: "l"(p), "r"(v) : "memory");
}
__device__ __forceinline__ unsigned ld_acquire_gpu(const unsigned* p) {
    unsigned v;
    asm volatile("ld.acquire.gpu.u32 %0, [%1];" : "=r"(v) : "l"(p) : "memory");
    return v;
}
__device__ __forceinline__ unsigned smem_u32(const void* p) {
    unsigned a;
    asm("{ .reg .u64 t; cvta.to.shared.u64 t, %1; cvt.u32.u64 %0, t; }"
        : "=r"(a) : "l"(p));
    return a;
}
__device__ __forceinline__ void mbar_init(unsigned a, unsigned cnt) {
    asm volatile("mbarrier.init.shared.b64 [%0], %1;" :: "r"(a), "r"(cnt) : "memory");
}
__device__ __forceinline__ void mbar_expect_tx(unsigned a, unsigned bytes) {
    asm volatile("mbarrier.arrive.expect_tx.shared.b64 _, [%0], %1;"
                 :: "r"(a), "r"(bytes) : "memory");
}
__device__ __forceinline__ void bulk_g2s(unsigned dst, const void* src,
                                         unsigned bytes, unsigned mbar) {
    asm volatile("cp.async.bulk.shared::cluster.global.mbarrier::complete_tx::bytes "
                 "[%0], [%1], %2, [%3];"
                 :: "r"(dst), "l"(src), "r"(bytes), "r"(mbar) : "memory");
}
__device__ __forceinline__ void mbar_wait_parity(unsigned a, unsigned phase) {
    unsigned done;
    asm volatile(
        "{\n\t.reg .pred p;\n\t"
        "mbarrier.try_wait.parity.acquire.cta.shared::cta.b64 p, [%1], %2;\n\t"
        "selp.b32 %0, 1, 0, p;\n\t}"
        : "=r"(done) : "r"(a), "r"(phase) : "memory");
    if (!done) {
        asm volatile(
            "{\n\t.reg .pred P1;\n\t"
            "WL_%=:\n\t"
            "mbarrier.try_wait.parity.acquire.cta.shared::cta.b64 P1, [%0], %1, 0x989680;\n\t"
            "@P1 bra.uni WD_%=;\n\t"
            "bra.uni WL_%=;\n\t"
            "WD_%=:\n\t}"
            :: "r"(a), "r"(phase) : "memory");
    }
}
// swizzled byte offset of (row 0..127, col 0..511 bf16) in a 128x512 tile
__device__ __forceinline__ uint32_t tile_off(int row, int col) {
    uint32_t byte = (uint32_t)(((row >> 3) + (col >> 6)*16)*1024
                               + (row & 7)*128 + (col & 63)*2);
    return byte ^ ((byte >> 3) & 0x70);
}
// within one staged 64-col block (col < 64), 128 rows
__device__ __forceinline__ uint32_t blk_off(int row, int col) {
    uint32_t byte = (uint32_t)(((row >> 3) << 10) + ((row & 7) << 7) + (col << 1));
    return byte ^ ((byte >> 3) & 0x70);
}
// 64-row x 128-col h plane chunk (16KB)
__device__ __forceinline__ uint32_t hplane_off(int row, int kl) {
    uint32_t byte = (uint32_t)((((row >> 3) + ((kl >> 6) << 3)) << 10)
                               + ((row & 7) << 7) + ((kl & 63) << 1));
    return byte ^ ((byte >> 3) & 0x70);
}
// 32-row x 512-col weight plane (32KB)
__device__ __forceinline__ uint32_t wplane_off(int row, int col) {
    uint32_t byte = (uint32_t)((((row >> 3) + ((col >> 6) << 2)) << 10)
                               + ((row & 7) << 7) + ((col & 63) << 1));
    return byte ^ ((byte >> 3) & 0x70);
}
__device__ __forceinline__ void split_bf16(float v, unsigned& h, unsigned& l) {
    __nv_bfloat16 hb = __float2bfloat16(v);
    float r = v - __bfloat162float(hb);
    __nv_bfloat16 lb = __float2bfloat16(r);
    h = (unsigned)__bfloat16_as_ushort(hb);
    l = (unsigned)__bfloat16_as_ushort(lb);
}
#define LDMATRIX_X4(r0, r1, r2, r3, addr) \
    asm volatile("ldmatrix.sync.aligned.m8n8.x4.shared.b16 {%0,%1,%2,%3}, [%4];" \
                 : "=r"(r0), "=r"(r1), "=r"(r2), "=r"(r3) : "r"(addr))
#define MMA_BF16(d, a, b) \
    asm volatile("mma.sync.aligned.m16n8k16.row.col.f32.bf16.bf16.f32 " \
                 "{%0,%1,%2,%3}, {%4,%5,%6,%7}, {%8,%9}, {%0,%1,%2,%3};" \
                 : "+f"((d)[0]), "+f"((d)[1]), "+f"((d)[2]), "+f"((d)[3]) \
                 : "r"((a)[0]), "r"((a)[1]), "r"((a)[2]), "r"((a)[3]), \
                   "r"((b)[0]), "r"((b)[1]))

// ---------------- prep: (B,T,K) -> [t][k][b], masked ----------------
__global__ void prep_kernel(const float* __restrict__ in, const int* __restrict__ len) {
    int idx = blockIdx.x * blockDim.x + threadIdx.x;
    if (idx >= TT*HH*BB) return;
    int b = idx & 63;
    int k = (idx >> 6) & 511;
    int t = idx >> 15;
    float v = 0.f;
    if (t < len[b]) v = in[((size_t)b*TT + t)*HH + k];
    g_xt[idx] = v;
}

// ------- pack W_hh into per-CTA swizzled split-bf16 B tiles [q32][k512] -------
__global__ void packwq_kernel(const float* __restrict__ weight) {
    int idx = blockIdx.x * blockDim.x + threadIdx.x;
    if (idx >= 4*128*32*64) return;
    int cu  = idx & 63;
    int row = (idx >> 6) & 31;
    int gq  = (idx >> 11) & 127;
    int l   = idx >> 18;
    unsigned h[8], lo[8];
    if (row < 20) {
        int hid = gq*4 + row/5;
        int g   = row % 5;
        const float* wsrc = weight + (size_t)l*LAYER_W_STRIDE + WHH_OFF;
        #pragma unroll
        for (int j = 0; j < 8; j++) {
            float v = wsrc[(size_t)(cu*8 + j)*G5 + g*512 + hid];
            split_bf16(v, h[j], lo[j]);
        }
    } else {
        #pragma unroll
        for (int j = 0; j < 8; j++) { h[j] = 0; lo[j] = 0; }
    }
    uint32_t off = wplane_off(row, cu*8);
    unsigned char* dst = g_whq + (size_t)(l*128 + gq)*65536;
    *(uint4*)(dst + off)         = make_uint4(h[0]|(h[1]<<16),  h[2]|(h[3]<<16),
                                              h[4]|(h[5]<<16),  h[6]|(h[7]<<16));
    *(uint4*)(dst + 32768 + off) = make_uint4(lo[0]|(lo[1]<<16), lo[2]|(lo[3]<<16),
                                              lo[4]|(lo[5]<<16), lo[6]|(lo[7]<<16));
}

// ---------------- pack W_ih^T into swizzled split-bf16 B tiles [n][k] ---------
__global__ void packwb_kernel(const float* __restrict__ weight) {
    int idx = blockIdx.x * blockDim.x + threadIdx.x;
    if (idx >= 4*24*128*64) return;
    int cu  = idx & 63;
    int row = (idx >> 6) & 127;
    int nt  = (idx >> 13) % 24;
    int l   = (idx >> 13) / 24;
    int g = nt*128 + row;
    const float* wsrc = weight + (size_t)l*LAYER_W_STRIDE;
    unsigned h[8], lo[8];
    #pragma unroll
    for (int j = 0; j < 8; j++) {
        float v = wsrc[(size_t)(cu*8 + j)*G6 + g];
        split_bf16(v, h[j], lo[j]);
    }
    size_t off = (size_t)(l*24 + nt)*8192 + (tile_off(row, cu*8) >> 4);
    g_wbh[off] = make_uint4(h[0]|(h[1]<<16),  h[2]|(h[3]<<16),
                            h[4]|(h[5]<<16),  h[6]|(h[7]<<16));
    g_wbl[off] = make_uint4(lo[0]|(lo[1]<<16), lo[2]|(lo[3]<<16),
                            lo[4]|(lo[5]<<16), lo[6]|(lo[7]<<16));
}

// ------- convert layer-0 input -> swizzled split-bf16 A tiles [m][k] ----------
__global__ void conva_kernel(const float* __restrict__ xsrc,
                             const int* __restrict__ len, int rev) {
    int idx = blockIdx.x * blockDim.x + threadIdx.x;
    if (idx >= 128*128*64) return;
    int cu   = idx & 63;
    int row  = (idx >> 6) & 127;
    int tile = idx >> 13;
    int b = row & 63;
    int t = tile*2 + (row >> 6);
    if (rev) { int L = len[b]; if (t < L) t = L - 1 - t; }
    unsigned h[8], lo[8];
    #pragma unroll
    for (int j = 0; j < 8; j++) {
        float v = xsrc[((size_t)t*HH + cu*8 + j)*BB + b];
        split_bf16(v, h[j], lo[j]);
    }
    size_t off = (size_t)tile*8192 + (tile_off(row, cu*8) >> 4);
    g_xah[off] = make_uint4(h[0]|(h[1]<<16),  h[2]|(h[3]<<16),
                            h[4]|(h[5]<<16),  h[6]|(h[7]<<16));
    g_xal[off] = make_uint4(lo[0]|(lo[1]<<16), lo[2]|(lo[3]<<16),
                            lo[4]|(lo[5]<<16), lo[6]|(lo[7]<<16));
}

// ---------------- bf16-split mma.sync xi GEMM (3-stage, R15 passing) ---------
__global__ __launch_bounds__(256)
void gemm_mma_kernel(const uint8_t* __restrict__ Ah, const uint8_t* __restrict__ Al,
                     const uint8_t* __restrict__ Bh, const uint8_t* __restrict__ Bl,
                     float* __restrict__ XI)
{
    extern __shared__ __align__(1024) uint8_t smg[];
    int tid = threadIdx.x;
    int lane = tid & 31, wid = tid >> 5;
    int wm = wid & 3, wn = wid >> 2;
    int mt = blockIdx.x, nt = blockIdx.y;
    unsigned sm = smem_u32(smg);
    unsigned mbf = sm + 196608u;

    if (tid == 0) {
        mbar_init(mbf, 1); mbar_init(mbf + 8, 1); mbar_init(mbf + 16, 1);
        asm volatile("fence.proxy.async.shared::cta;" ::: "memory");
    }
    __syncthreads();

    const uint8_t* aH = Ah + (size_t)mt*131072;
    const uint8_t* aL = Al + (size_t)mt*131072;
    const uint8_t* bH = Bh + (size_t)nt*131072;
    const uint8_t* bL = Bl + (size_t)nt*131072;

    if (tid == 0) {
        #pragma unroll
        for (int s = 0; s < 3; s++) {
            unsigned sb = sm + (unsigned)s*65536u;
            mbar_expect_tx(mbf + 8*s, 65536u);
            bulk_g2s(sb,           aH + s*16384, 16384u, mbf + 8*s);
            bulk_g2s(sb + 16384u,  aL + s*16384, 16384u, mbf + 8*s);
            bulk_g2s(sb + 32768u,  bH + s*16384, 16384u, mbf + 8*s);
            bulk_g2s(sb + 49152u,  bL + s*16384, 16384u, mbf + 8*s);
        }
    }

    float acc[2][8][4];
    #pragma unroll
    for (int mi = 0; mi < 2; mi++)
        #pragma unroll
        for (int nj = 0; nj < 8; nj++)
            #pragma unroll
            for (int q = 0; q < 4; q++) acc[mi][nj][q] = 0.f;

    int r  = lane & 7;
    int ts = lane >> 3;
    int arow0 = wm*32 + r + ((ts & 1) << 3);
    int akadd = (ts >> 1) << 3;
    int brow0 = wn*64 + r + ((ts >> 1) << 3);
    int bkadd = (ts & 1) << 3;

    for (int s = 0; s < 8; s++) {
        int p = s % 3;
        unsigned ph = (unsigned)((s / 3) & 1);
        mbar_wait_parity(mbf + 8*p, ph);
        unsigned sb  = sm + (unsigned)p*65536u;
        unsigned sAh = sb, sAl = sb + 16384u;
        unsigned sBh = sb + 32768u, sBl = sb + 49152u;

        #pragma unroll
        for (int j = 0; j < 4; j++) {
            int kc = j*16 + akadd;
            uint32_t ah0[4], ah1[4], al0[4], al1[4];
            {
                unsigned o0 = blk_off(arow0,      kc);
                unsigned o1 = blk_off(arow0 + 16, kc);
                LDMATRIX_X4(ah0[0], ah0[1], ah0[2], ah0[3], sAh + o0);
                LDMATRIX_X4(ah1[0], ah1[1], ah1[2], ah1[3], sAh + o1);
                LDMATRIX_X4(al0[0], al0[1], al0[2], al0[3], sAl + o0);
                LDMATRIX_X4(al1[0], al1[1], al1[2], al1[3], sAl + o1);
            }
            int kb = j*16 + bkadd;
            uint32_t bh[8][2], bl[8][2];
            #pragma unroll
            for (int p4 = 0; p4 < 4; p4++) {
                unsigned ob = blk_off(brow0 + p4*16, kb);
                LDMATRIX_X4(bh[2*p4][0], bh[2*p4][1], bh[2*p4+1][0], bh[2*p4+1][1],
                            sBh + ob);
                LDMATRIX_X4(bl[2*p4][0], bl[2*p4][1], bl[2*p4+1][0], bl[2*p4+1][1],
                            sBl + ob);
            }
            #pragma unroll
            for (int nj = 0; nj < 8; nj++) {
                MMA_BF16(acc[0][nj], ah0, bh[nj]);
                MMA_BF16(acc[1][nj], ah1, bh[nj]);
                MMA_BF16(acc[0][nj], ah0, bl[nj]);
                MMA_BF16(acc[1][nj], ah1, bl[nj]);
                MMA_BF16(acc[0][nj], al0, bh[nj]);
                MMA_BF16(acc[1][nj], al1, bh[nj]);
            }
        }
        __syncthreads();
        if (tid == 0 && s + 3 < 8) {
            int s2 = s + 3;
            mbar_expect_tx(mbf + 8*p, 65536u);
            bulk_g2s(sb,          aH + s2*16384, 16384u, mbf + 8*p);
            bulk_g2s(sb + 16384u, aL + s2*16384, 16384u, mbf + 8*p);
            bulk_g2s(sb + 32768u, bH + s2*16384, 16384u, mbf + 8*p);
            bulk_g2s(sb + 49152u, bL + s2*16384, 16384u, mbf + 8*p);
        }
    }

    int g4 = lane >> 2, t4 = lane & 3;
    #pragma unroll
    for (int mi = 0; mi < 2; mi++) {
        #pragma unroll
        for (int half = 0; half < 2; half++) {
            int m = mt*128 + wm*32 + mi*16 + g4 + half*8;
            int t = m >> 6, b = m & 63;
            float* xo = XI + ((size_t)t*G6 + nt*128 + wn*64 + t4*2)*64 + b;
            #pragma unroll
            for (int nj = 0; nj < 8; nj++) {
                xo[(size_t)(nj*8)*64]       = acc[mi][nj][half*2];
                xo[(size_t)(nj*8 + 1)*64]   = acc[mi][nj][half*2 + 1];
            }
        }
    }
}

// ---------------- persistent per-layer recurrence (R15 verbatim + fused A) ---
// hi/lo sub-chunk staging; warp (wm,wn) D[m16(b) x n16(q)] over K=512.
// NEW: epilogue also writes next layer's pre-swizzled split-bf16 A tile
// (reversal composed for the next layer) — replaces conva for layers 1..3.
__global__ __launch_bounds__(288)
void lstm_layer_kernel(const float* __restrict__ xi_base,
                       const unsigned char* __restrict__ wq,
                       const float* __restrict__ bias,
                       const int*   __restrict__ len,
                       unsigned char* __restrict__ hbuf0,
                       unsigned char* __restrict__ hbuf1,
                       float* __restrict__ y,
                       unsigned char* __restrict__ nxtAh,
                       unsigned char* __restrict__ nxtAl,
                       int rev, int nrev, int wA)
{
    extern __shared__ float smf[];
    int tid = threadIdx.x;
    int hid0 = blockIdx.x * 4;
    int grp  = blockIdx.x >> 5;

    unsigned smbase = smem_u32(smf);
    unsigned smW    = smbase + OWQ_F*4;
    unsigned smH    = smbase + OH_F*4;
    unsigned mbar0  = smbase + OFF_MBAR_B;   // 8 mbars: [ch].hi @16ch, [ch].lo @16ch+8

    int lane = tid & 31, wid = tid >> 5;
    int wm = wid & 3, wn = (wid >> 2) & 1;
    int hl_o = (tid >> 6) & 3;
    int b_o  = tid & 63;
    int hid_o = hid0 + hl_o;

    if (tid < 256) {
        const uint4* ws = (const uint4*)(wq + (size_t)blockIdx.x*65536);
        uint4* wd = (uint4*)smf;
        #pragma unroll
        for (int i = 0; i < 16; i++) wd[tid + i*256] = ws[tid + i*256];
    }
    if (tid == 256) {
        #pragma unroll
        for (int c = 0; c < 8; c++) mbar_init(mbar0 + 8*c, 1);
        asm volatile("fence.proxy.async.shared::cta;" ::: "memory");
    }

    float bval[5] = {0.f, 0.f, 0.f, 0.f, 0.f};
    int L = 0;
    float xiv[6] = {0.f, 0.f, 0.f, 0.f, 0.f, 0.f};
    if (tid < 256) {
        #pragma unroll
        for (int g = 0; g < 5; g++) bval[g] = bias[g*512 + hid_o];
        L = len[b_o];
        #pragma unroll
        for (int g = 0; g < 6; g++)
            xiv[g] = __ldcs(xi_base + (size_t)(g*512 + hid_o)*BB + b_o);
    }
    float c = 0.0f;

    unsigned char* hin  = hbuf0;
    unsigned char* hout = hbuf1;

    int r  = lane & 7;
    int ts = lane >> 3;
    int arow = wm*16 + r + ((ts & 1) << 3);
    int ak   = (ts >> 1) << 3;
    int brow = wn*16 + r + ((ts >> 1) << 3);
    int bk   = (ts & 1) << 3;

    __syncthreads();

    if (tid == 256) {
        #pragma unroll
        for (int ch = 0; ch < 4; ch++) {
            mbar_expect_tx(mbar0 + 16*ch, 16384u);
            bulk_g2s(smH + ch*32768u, hin + ch*32768, 16384u, mbar0 + 16*ch);
            mbar_expect_tx(mbar0 + 16*ch + 8, 16384u);
            bulk_g2s(smH + ch*32768u + 16384u, hin + ch*32768 + 16384, 16384u,
                     mbar0 + 16*ch + 8);
        }
    }

    for (int s = 0; s < TT; s++) {
        unsigned phase = (unsigned)(s & 1);
        unsigned hi16 = 0, lo16 = 0;

        if (tid < 256) {
            float acc[2][4];
            #pragma unroll
            for (int nj = 0; nj < 2; nj++)
                #pragma unroll
                for (int q = 0; q < 4; q++) acc[nj][q] = 0.f;

            #pragma unroll
            for (int ch = 0; ch < 4; ch++) {
                unsigned sAh = smH + ch*32768u;
                unsigned sAl = sAh + 16384u;
                uint32_t bhsv[8][2][2];

                mbar_wait_parity(mbar0 + 16*ch, phase);       // hi plane ready
                #pragma unroll
                for (int j = 0; j < 8; j++) {
                    unsigned ao = hplane_off(arow, j*16 + ak);
                    uint32_t ah[4];
                    LDMATRIX_X4(ah[0], ah[1], ah[2], ah[3], sAh + ao);
                    int kg = ch*128 + j*16 + bk;
                    unsigned bo = wplane_off(brow, kg);
                    uint32_t bl[2][2];
                    LDMATRIX_X4(bhsv[j][0][0], bhsv[j][0][1],
                                bhsv[j][1][0], bhsv[j][1][1], smW + bo);
                    LDMATRIX_X4(bl[0][0], bl[0][1], bl[1][0], bl[1][1],
                                smW + 32768u + bo);
                    #pragma unroll
                    for (int nj = 0; nj < 2; nj++) {
                        MMA_BF16(acc[nj], ah, bhsv[j][nj]);
                        MMA_BF16(acc[nj], ah, bl[nj]);
                    }
                }
                mbar_wait_parity(mbar0 + 16*ch + 8, phase);   // lo plane ready
                #pragma unroll
                for (int j = 0; j < 8; j++) {
                    unsigned ao = hplane_off(arow, j*16 + ak);
                    uint32_t al[4];
                    LDMATRIX_X4(al[0], al[1], al[2], al[3], sAl + ao);
                    #pragma unroll
                    for (int nj = 0; nj < 2; nj++)
                        MMA_BF16(acc[nj], al, bhsv[j][nj]);
                }
            }

            float* db = smf + OD_F;
            int drow = wm*16 + (lane >> 2);
            int dcol = wn*16 + (lane & 3)*2;
            #pragma unroll
            for (int nj = 0; nj < 2; nj++) {
                db[drow*34 + dcol + nj*8]       = acc[nj][0];
                db[drow*34 + dcol + nj*8 + 1]   = acc[nj][1];
                db[(drow+8)*34 + dcol + nj*8]   = acc[nj][2];
                db[(drow+8)*34 + dcol + nj*8+1] = acc[nj][3];
            }
        }
        __syncthreads();                              // sync A

        float hn = 0.f;
        if (tid < 256) {
            const float* db = smf + OD_F + b_o*34 + hl_o*5;
            float gv[5];
            #pragma unroll
            for (int g = 0; g < 5; g++) gv[g] = xiv[g] + bval[g] + db[g];

            float ig = sigmoidf_(gv[0]);
            float fg = sigmoidf_(gv[1]);
            float gc = tanhf(gv[2]);
            float og = sigmoidf_(gv[3]);
            float rg = sigmoidf_(gv[4]);
            float lin = xiv[5];

            float cn;
            if (s < L) {
                cn = fg*c + ig*gc;
                hn = rg*(og*tanhf(cn)) + (1.f - rg)*lin;
            } else {
                cn = 0.f; hn = 0.f;
            }
            c = cn;
            split_bf16(hn, hi16, lo16);
            int chn = hid_o >> 7, kl = hid_o & 127;
            uint32_t loc = hplane_off(b_o, kl);
            *(uint16_t*)(hout + chn*32768 + loc)          = (uint16_t)hi16;
            *(uint16_t*)(hout + chn*32768 + 16384 + loc)  = (uint16_t)lo16;
        }
        __syncthreads();                              // sync B

        int dst = rev ? ((s < L) ? (L - 1 - s) : s) : s;

        if (s != TT-1) {
            if (tid == 0)
                red_add_release_gpu(&g_cnt[grp], 1u);

            if (tid < 256) {
                y[((size_t)dst*HH + hid_o)*BB + b_o] = hn;
                if (wA) {   // fused conva for next layer (reversal composed)
                    int tw = nrev ? ((dst < L) ? (L - 1 - dst) : dst) : dst;
                    size_t tb = (size_t)(tw >> 1)*131072
                              + tile_off(((tw & 1) << 6) + b_o, hid_o);
                    *(uint16_t*)(nxtAh + tb) = (uint16_t)hi16;
                    *(uint16_t*)(nxtAl + tb) = (uint16_t)lo16;
                }
                const float* xs = xi_base + (size_t)(s+1)*G6*BB;
                #pragma unroll
                for (int g = 0; g < 6; g++)
                    xiv[g] = __ldcs(xs + (size_t)(g*512 + hid_o)*BB + b_o);
            }

            if (tid == 256) {
                const unsigned char* hsrc = hout;
                unsigned target = 32u * (unsigned)(s + 1);
                #pragma unroll
                for (int ch = 0; ch < 4; ch++) {
                    while (ld_acquire_gpu(&g_cnt[ch]) < target) __nanosleep(32);
                    mbar_expect_tx(mbar0 + 16*ch, 16384u);
                    bulk_g2s(smH + ch*32768u, hsrc + ch*32768, 16384u,
                             mbar0 + 16*ch);
                    mbar_expect_tx(mbar0 + 16*ch + 8, 16384u);
                    bulk_g2s(smH + ch*32768u + 16384u, hsrc + ch*32768 + 16384,
                             16384u, mbar0 + 16*ch + 8);
                }
            }
        } else if (tid < 256) {
            y[((size_t)dst*HH + hid_o)*BB + b_o] = hn;
            if (wA) {
                int tw = nrev ? ((dst < L) ? (L - 1 - dst) : dst) : dst;
                size_t tb = (size_t)(tw >> 1)*131072
                          + tile_off(((tw & 1) << 6) + b_o, hid_o);
                *(uint16_t*)(nxtAh + tb) = (uint16_t)hi16;
                *(uint16_t*)(nxtAl + tb) = (uint16_t)lo16;
            }
        }

        unsigned char* tmp = hin; hin = hout; hout = tmp;
    }
}

// ---------------- final: [t][k][b] -> (B,T,K) ----------------
__global__ void out_kernel(const float* __restrict__ xt, float* __restrict__ out) {
    int idx = blockIdx.x * blockDim.x + threadIdx.x;
    if (idx >= TT*HH*BB) return;
    int k = idx & 511;
    int t = (idx >> 9) & 255;
    int b = idx >> 17;
    out[idx] = xt[((size_t)t*HH + k)*BB + b];
}

// ---------------- launch ----------------
extern "C" void kernel_launch(void* const* d_in, const int* in_sizes, int n_in,
                              void* d_out, int out_size)
{
    const float* inputs = nullptr;
    const float* weight = nullptr;
    const float* biasp  = nullptr;
    const int*   len    = nullptr;
    for (int i = 0; i < n_in; i++) {
        switch (in_sizes[i]) {
            case TT*BB*HH:  inputs = (const float*)d_in[i]; break;  // 8388608
            case 11534336:  weight = (const float*)d_in[i]; break;
            case 4*G5:      biasp  = (const float*)d_in[i]; break;  // 10240
            case BB:        len    = (const int*)  d_in[i]; break;  // 64
        }
    }

    float *pxt, *pyt, *pxi;
    unsigned char *phb0, *phb1, *pwhq;
    unsigned* pcnt;
    uint4 *pwbh, *pwbl, *pxah, *pxal;
    cudaGetSymbolAddress((void**)&pxt,  g_xt);
    cudaGetSymbolAddress((void**)&pyt,  g_yt);
    cudaGetSymbolAddress((void**)&pxi,  g_xi);
    cudaGetSymbolAddress((void**)&phb0, g_hb0);
    cudaGetSymbolAddress((void**)&phb1, g_hb1);
    cudaGetSymbolAddress((void**)&pwhq, g_whq);
    cudaGetSymbolAddress((void**)&pcnt, g_cnt);
    cudaGetSymbolAddress((void**)&pwbh, g_wbh);
    cudaGetSymbolAddress((void**)&pwbl, g_wbl);
    cudaGetSymbolAddress((void**)&pxah, g_xah);
    cudaGetSymbolAddress((void**)&pxal, g_xal);

    cudaFuncSetAttribute(lstm_layer_kernel,
                         cudaFuncAttributeMaxDynamicSharedMemorySize, SMEM_LSTM);
    cudaFuncSetAttribute(gemm_mma_kernel,
                         cudaFuncAttributeMaxDynamicSharedMemorySize, SMEM_GMM);

    prep_kernel<<<(TT*HH*BB + 255)/256, 256>>>(inputs, len);
    packwq_kernel<<<(4*128*32*64)/256, 256>>>(weight);
    packwb_kernel<<<(4*24*128*64)/256, 256>>>(weight);

    float* xin  = pxt;
    float* yout = pyt;
    for (int l = 0; l < 4; l++) {
        int rev  = l & 1;
        int nrev = (l + 1) & 1;
        if (l == 0)
            conva_kernel<<<(128*128*64)/256, 256>>>(xin, len, rev);
        gemm_mma_kernel<<<dim3(128, 24), 256, SMEM_GMM>>>(
            (const uint8_t*)pxah, (const uint8_t*)pxal,
            (const uint8_t*)(pwbh + (size_t)l*24*8192),
            (const uint8_t*)(pwbl + (size_t)l*24*8192),
            pxi);
        cudaMemsetAsync(phb0, 0, 4*32768);
        cudaMemsetAsync(pcnt, 0, 4*sizeof(unsigned));
        lstm_layer_kernel<<<NCTA, 288, SMEM_LSTM>>>(
            pxi, pwhq + (size_t)l*128*65536, biasp + (size_t)l*G5,
            len, phb0, phb1, yout,
            (unsigned char*)pxah, (unsigned char*)pxal,
            rev, nrev, (l < 3) ? 1 : 0);
        float* tmp = xin; xin = yout; yout = tmp;
    }
    out_kernel<<<(TT*HH*BB + 255)/256, 256>>>(xin, (float*)d_out);
}